// round 15
// baseline (speedup 1.0000x reference)
#include <cuda_runtime.h>
#include <cuda_bf16.h>
#include <cuda_fp16.h>

#define NN 50000
#define NE 600000
#define DD 128
#define NT 391            // 128-row tiles covering 50048 rows
#define LDA 136           // padded smem row (bf16 units): 272B, conflict-free ldmatrix
#define NSB 49            // scan blocks: 49 * 1024 >= NN
#define NPREP (NN * DD / 4)   // 1.6M quads

// ---------------- scratch (device globals; no allocation allowed) ----------------
// counters zero at module load; re-zeroed inside k_fill_prep each call
__device__ int   g_out_cnt[NN];
__device__ int   g_in_cnt[NN];
__device__ int   g_row_off[NN + 1];
__device__ int   g_cursor[NN];
__device__ int   g_csr_src[NE];
__device__ float g_src_norm[NN];
__device__ float g_dst_norm[NN];
// fp16 feature storage, prescaled by src_norm
__device__ __align__(16) __half g_f16[NN * DD];   // layer-0 input
__device__ __align__(16) __half g_p0[NN * DD];    // ping-pong prescaled h
__device__ __align__(16) __half g_p1[NN * DD];
// bf16 split of W (k x n row-major), per layer
__device__ __align__(16) unsigned short g_wh16[4 * DD * DD];
__device__ __align__(16) unsigned short g_wl16[4 * DD * DD];

// ---------------- PTX helpers (base sm_100 compatible only!) ----------------
__device__ __forceinline__ unsigned s2u(const void* p) {
    unsigned r;
    asm("{ .reg .u64 t; cvta.to.shared.u64 t, %1; cvt.u32.u64 %0, t; }" : "=r"(r) : "l"(p));
    return r;
}
#define LDSM_X4(r, a)                                                         \
    asm volatile("ldmatrix.sync.aligned.m8n8.x4.shared.b16 {%0,%1,%2,%3}, [%4];" \
        : "=r"((r)[0]), "=r"((r)[1]), "=r"((r)[2]), "=r"((r)[3]) : "r"(a))
#define LDSM_X4T(r, a)                                                        \
    asm volatile("ldmatrix.sync.aligned.m8n8.x4.trans.shared.b16 {%0,%1,%2,%3}, [%4];" \
        : "=r"((r)[0]), "=r"((r)[1]), "=r"((r)[2]), "=r"((r)[3]) : "r"(a))
#define MMA16816(c, a, b0_, b1_)                                              \
    asm volatile("mma.sync.aligned.m16n8k16.row.col.f32.bf16.bf16.f32 "       \
        "{%0,%1,%2,%3},{%4,%5,%6,%7},{%8,%9},{%0,%1,%2,%3};"                  \
        : "+f"((c)[0]), "+f"((c)[1]), "+f"((c)[2]), "+f"((c)[3])              \
        : "r"((a)[0]), "r"((a)[1]), "r"((a)[2]), "r"((a)[3]), "r"(b0_), "r"(b1_))

// add 4 halves (uint2) into float4 accumulator
__device__ __forceinline__ void acc_h4(float4& A, uint2 u) {
    float2 a = __half22float2(*(__half2*)&u.x);
    float2 b = __half22float2(*(__half2*)&u.y);
    A.x += a.x; A.y += a.y; A.z += b.x; A.w += b.y;
}

// ---------------- launch 0: degree count + W split (fused) ----------------
__global__ void k_count_w(const int* __restrict__ src, const int* __restrict__ dst,
                          const float* __restrict__ W) {
    int e = blockIdx.x * blockDim.x + threadIdx.x;
    if (e < NE) {
        atomicAdd(&g_out_cnt[src[e]], 1);
        atomicAdd(&g_in_cnt[dst[e]], 1);
    }
    if (e < 4 * DD * DD) {
        float v = __ldg(W + e);
        __nv_bfloat16 hi = __float2bfloat16(v);
        float lo = v - __bfloat162float(hi);
        g_wh16[e] = __bfloat16_as_ushort(hi);
        g_wl16[e] = __bfloat16_as_ushort(__float2bfloat16(lo));
    }
}

// ---------------- launch 1: one-kernel scan (self-computed base) + norms ----------
__global__ __launch_bounds__(1024) void k_scan2() {
    __shared__ int sd[1024];
    __shared__ int sbase;
    int t = threadIdx.x, b = blockIdx.x;
    int i = b * 1024 + t;
    int incnt = (i < NN) ? g_in_cnt[i] : 0;
    int part = 0;
    for (int k = t; k < b * 1024; k += 1024) part += g_in_cnt[k];
    sd[t] = part;
    __syncthreads();
#pragma unroll
    for (int s = 512; s > 0; s >>= 1) {
        if (t < s) sd[t] += sd[t + s];
        __syncthreads();
    }
    if (t == 0) sbase = sd[0];
    __syncthreads();
    int base = sbase;
    __syncthreads();
    sd[t] = incnt;
    __syncthreads();
#pragma unroll
    for (int off = 1; off < 1024; off <<= 1) {
        int v = (t >= off) ? sd[t - off] : 0;
        __syncthreads();
        sd[t] += v;
        __syncthreads();
    }
    int excl = sd[t] - incnt;
    if (i < NN) {
        int o = base + excl;
        g_row_off[i] = o;
        g_cursor[i]  = o;
        g_src_norm[i] = rsqrtf((float)max(g_out_cnt[i], 1));
        g_dst_norm[i] = rsqrtf((float)max(incnt, 1));
    }
    if (b == NSB - 1 && t == 1023) g_row_off[NN] = base + sd[1023];
}

// ---------------- launch 2: CSR fill + counter re-zero + feat prescale->fp16 -----
__global__ void k_fill_prep(const int* __restrict__ src, const int* __restrict__ dst,
                            const float* __restrict__ feat) {
    int e = blockIdx.x * blockDim.x + threadIdx.x;   // grid sized for NPREP
    if (e < NE) {
        int d = dst[e];
        int p = atomicAdd(&g_cursor[d], 1);
        g_csr_src[p] = src[e];
    }
    if (e < NN) { g_out_cnt[e] = 0; g_in_cnt[e] = 0; }
    if (e < NPREP) {
        int row = e >> 5;
        float sn = __ldg(&g_src_norm[row]);
        float4 v = __ldg((const float4*)feat + e);
        __half2 a = __floats2half2_rn(v.x * sn, v.y * sn);
        __half2 b = __floats2half2_rn(v.z * sn, v.w * sn);
        uint2 u; u.x = *(unsigned*)&a; u.y = *(unsigned*)&b;
        *((uint2*)g_f16 + e) = u;
    }
}

// ---------------- fused aggregate + GEMM: fp16 rows, 8-edge pipeline -------------
// CTA t: nodes [t*128, t*128+128). 1024 threads (32 warps), 1 CTA/SM.
// Phase 1: warp w sums fp16 rows for nodes w*4..w*4+3. Indices via int4 vector
//          loads (one-iter prefetch); 8 rows in flight; 4 independent fp32 accs.
// Phase 2: 32 warps mma, warp tile 32m x 16n, 3-term bf16 split (unchanged).
#define FSMEM (4 * DD * LDA * 2)

__global__ __launch_bounds__(1024, 1) void k_fused(
        int sel, int layer, const float* __restrict__ bias,
        float* __restrict__ ext_out, int out_sel) {
    extern __shared__ unsigned short smx[];
    unsigned short* sWh = smx;
    unsigned short* sWl = smx + DD * LDA;
    unsigned short* sAh = smx + 2 * DD * LDA;
    unsigned short* sAl = smx + 3 * DD * LDA;

    int tid = threadIdx.x, lane = tid & 31, w = tid >> 5;
    int t = blockIdx.x;
    const uint2* h2 = (const uint2*)(sel == 0 ? g_f16 : (sel == 1 ? g_p0 : g_p1));

    // stage W (1024 threads x 2 uint4 each per array)
    {
        const uint4* w_h = (const uint4*)(g_wh16 + layer * DD * DD);
        const uint4* w_l = (const uint4*)(g_wl16 + layer * DD * DD);
#pragma unroll
        for (int i = 0; i < 2; i++) {
            int li = tid + i * 1024;
            int r = li >> 4, c = li & 15;
            int d = r * LDA + c * 8;
            *(uint4*)&sWh[d] = w_h[li];
            *(uint4*)&sWl[d] = w_l[li];
        }
    }

    // ---------------- phase 1: sum fp16 rows, 4 nodes per warp -------------------
#pragma unroll
    for (int q = 0; q < 4; q++) {
        int r = w * 4 + q;              // local row 0..127
        int gw = t * DD + r;
        float4 acc = make_float4(0.f, 0.f, 0.f, 0.f);
        if (gw < NN) {
            int beg = __ldg(&g_row_off[gw]), end = __ldg(&g_row_off[gw + 1]);
            int j = beg;
            float4 A0 = make_float4(0.f, 0.f, 0.f, 0.f);
            float4 A1 = make_float4(0.f, 0.f, 0.f, 0.f);
            float4 A2 = make_float4(0.f, 0.f, 0.f, 0.f);
            float4 A3 = make_float4(0.f, 0.f, 0.f, 0.f);
            // align j to 4 for int4 index loads
            for (; j < end && (j & 3); j++) {
                int u = __ldg(&g_csr_src[j]);
                acc_h4(A0, __ldg(&h2[u * 32 + lane]));
            }
            // invariant: if j+8<=end then c0,c1 hold indices j..j+7
            int4 c0, c1;
            if (j + 8 <= end) {
                c0 = __ldg((const int4*)(g_csr_src + j));
                c1 = __ldg((const int4*)(g_csr_src + j + 4));
            }
            for (; j + 16 <= end; j += 8) {
                int4 n0 = __ldg((const int4*)(g_csr_src + j + 8));
                int4 n1 = __ldg((const int4*)(g_csr_src + j + 12));
                uint2 u0 = __ldg(&h2[c0.x * 32 + lane]);
                uint2 u1 = __ldg(&h2[c0.y * 32 + lane]);
                uint2 u2 = __ldg(&h2[c0.z * 32 + lane]);
                uint2 u3 = __ldg(&h2[c0.w * 32 + lane]);
                uint2 u4 = __ldg(&h2[c1.x * 32 + lane]);
                uint2 u5 = __ldg(&h2[c1.y * 32 + lane]);
                uint2 u6 = __ldg(&h2[c1.z * 32 + lane]);
                uint2 u7 = __ldg(&h2[c1.w * 32 + lane]);
                acc_h4(A0, u0); acc_h4(A1, u1); acc_h4(A2, u2); acc_h4(A3, u3);
                acc_h4(A0, u4); acc_h4(A1, u5); acc_h4(A2, u6); acc_h4(A3, u7);
                c0 = n0; c1 = n1;
            }
            if (j + 8 <= end) {          // consume pending prefetch
                uint2 u0 = __ldg(&h2[c0.x * 32 + lane]);
                uint2 u1 = __ldg(&h2[c0.y * 32 + lane]);
                uint2 u2 = __ldg(&h2[c0.z * 32 + lane]);
                uint2 u3 = __ldg(&h2[c0.w * 32 + lane]);
                uint2 u4 = __ldg(&h2[c1.x * 32 + lane]);
                uint2 u5 = __ldg(&h2[c1.y * 32 + lane]);
                uint2 u6 = __ldg(&h2[c1.z * 32 + lane]);
                uint2 u7 = __ldg(&h2[c1.w * 32 + lane]);
                acc_h4(A0, u0); acc_h4(A1, u1); acc_h4(A2, u2); acc_h4(A3, u3);
                acc_h4(A0, u4); acc_h4(A1, u5); acc_h4(A2, u6); acc_h4(A3, u7);
                j += 8;
            }
            if (j + 4 <= end) {
                int4 c = __ldg((const int4*)(g_csr_src + j));
                uint2 u0 = __ldg(&h2[c.x * 32 + lane]);
                uint2 u1 = __ldg(&h2[c.y * 32 + lane]);
                uint2 u2 = __ldg(&h2[c.z * 32 + lane]);
                uint2 u3 = __ldg(&h2[c.w * 32 + lane]);
                acc_h4(A0, u0); acc_h4(A1, u1); acc_h4(A2, u2); acc_h4(A3, u3);
                j += 4;
            }
            for (; j < end; j++) {
                int u = __ldg(&g_csr_src[j]);
                acc_h4(A0, __ldg(&h2[u * 32 + lane]));
            }
            float dn = __ldg(&g_dst_norm[gw]);
            acc.x += ((A0.x + A1.x) + (A2.x + A3.x)); acc.x *= dn;
            acc.y += ((A0.y + A1.y) + (A2.y + A3.y)); acc.y *= dn;
            acc.z += ((A0.z + A1.z) + (A2.z + A3.z)); acc.z *= dn;
            acc.w += ((A0.w + A1.w) + (A2.w + A3.w)); acc.w *= dn;
        }
        // split to bf16 hi/lo, store to smem in ldmatrix layout
        __nv_bfloat16 hx = __float2bfloat16(acc.x), hy = __float2bfloat16(acc.y);
        __nv_bfloat16 hz = __float2bfloat16(acc.z), hw = __float2bfloat16(acc.w);
        ushort4 vh, vl;
        vh.x = __bfloat16_as_ushort(hx); vh.y = __bfloat16_as_ushort(hy);
        vh.z = __bfloat16_as_ushort(hz); vh.w = __bfloat16_as_ushort(hw);
        vl.x = __bfloat16_as_ushort(__float2bfloat16(acc.x - __bfloat162float(hx)));
        vl.y = __bfloat16_as_ushort(__float2bfloat16(acc.y - __bfloat162float(hy)));
        vl.z = __bfloat16_as_ushort(__float2bfloat16(acc.z - __bfloat162float(hz)));
        vl.w = __bfloat16_as_ushort(__float2bfloat16(acc.w - __bfloat162float(hw)));
        *(ushort4*)&sAh[r * LDA + lane * 4] = vh;
        *(ushort4*)&sAl[r * LDA + lane * 4] = vl;
    }
    __syncthreads();

    // ---------------- phase 2: 3-term mma, warp tile 32m x 16n ----------------
    int mw = w & 3, nw = w >> 2;     // 4 m-groups x 8 n-groups

    float acc2[2][2][4];
#pragma unroll
    for (int mt = 0; mt < 2; mt++)
#pragma unroll
        for (int nt = 0; nt < 2; nt++)
#pragma unroll
            for (int q = 0; q < 4; q++) acc2[mt][nt][q] = 0.f;

    unsigned aH[2], aL[2];
#pragma unroll
    for (int mt = 0; mt < 2; mt++) {
        int r = mw * 32 + mt * 16 + (lane & 15);
        aH[mt] = s2u(&sAh[r * LDA + (lane >> 4) * 8]);
        aL[mt] = s2u(&sAl[r * LDA + (lane >> 4) * 8]);
    }
    unsigned bB = (lane < 16) ? s2u(&sWh[(lane & 15) * LDA + nw * 16])
                              : s2u(&sWl[(lane & 15) * LDA + nw * 16]);

#pragma unroll
    for (int ks = 0; ks < 8; ks++) {
        unsigned ah[2][4], al[2][4];
#pragma unroll
        for (int mt = 0; mt < 2; mt++) {
            LDSM_X4(ah[mt], aH[mt] + ks * 32);
            LDSM_X4(al[mt], aL[mt] + ks * 32);
        }
#pragma unroll
        for (int nt = 0; nt < 2; nt++) {
            unsigned b[4];                 // b[0..1]=Wh frag, b[2..3]=Wl frag
            LDSM_X4T(b, bB + ks * 16 * LDA * 2 + nt * 16);
#pragma unroll
            for (int mt = 0; mt < 2; mt++) {
                MMA16816(acc2[mt][nt], ah[mt], b[0], b[1]);
                MMA16816(acc2[mt][nt], ah[mt], b[2], b[3]);
                MMA16816(acc2[mt][nt], al[mt], b[0], b[1]);
            }
        }
    }

    // epilogue: layers 0-2 -> fp16 prescaled by src_norm; final -> fp32 ext
    __half* outh = (out_sel == 1) ? g_p0 : g_p1;
#pragma unroll
    for (int mt = 0; mt < 2; mt++) {
        int r0 = t * DD + mw * 32 + mt * 16 + (lane >> 2);
        int r1 = r0 + 8;
        float sn0 = 1.f, sn1 = 1.f;
        if (out_sel != 0) {
            if (r0 < NN) sn0 = __ldg(&g_src_norm[r0]);
            if (r1 < NN) sn1 = __ldg(&g_src_norm[r1]);
        }
#pragma unroll
        for (int nt = 0; nt < 2; nt++) {
            int col = nw * 16 + nt * 8 + (lane & 3) * 2;
            float2 bb = *(const float2*)&bias[col];
            if (out_sel == 0) {
                if (r0 < NN) {
                    float2 v; v.x = acc2[mt][nt][0] + bb.x; v.y = acc2[mt][nt][1] + bb.y;
                    *(float2*)&ext_out[(size_t)r0 * DD + col] = v;
                }
                if (r1 < NN) {
                    float2 v; v.x = acc2[mt][nt][2] + bb.x; v.y = acc2[mt][nt][3] + bb.y;
                    *(float2*)&ext_out[(size_t)r1 * DD + col] = v;
                }
            } else {
                if (r0 < NN) {
                    __half2 v = __floats2half2_rn((acc2[mt][nt][0] + bb.x) * sn0,
                                                  (acc2[mt][nt][1] + bb.y) * sn0);
                    *(__half2*)&outh[(size_t)r0 * DD + col] = v;
                }
                if (r1 < NN) {
                    __half2 v = __floats2half2_rn((acc2[mt][nt][2] + bb.x) * sn1,
                                                  (acc2[mt][nt][3] + bb.y) * sn1);
                    *(__half2*)&outh[(size_t)r1 * DD + col] = v;
                }
            }
        }
    }
}

// ---------------- launch ----------------
extern "C" void kernel_launch(void* const* d_in, const int* in_sizes, int n_in,
                              void* d_out, int out_size) {
    const float* feat = (const float*)d_in[0];
    const int*   src  = (const int*)d_in[1];
    const int*   dst  = (const int*)d_in[2];
    const float* W    = (const float*)d_in[3];
    const float* b    = (const float*)d_in[4];
    float* out = (float*)d_out;

    cudaFuncSetAttribute(k_fused, cudaFuncAttributeMaxDynamicSharedMemorySize, FSMEM);

    const int TB = 256;
    k_count_w<<<(NE + TB - 1) / TB, TB>>>(src, dst, W);            // 0
    k_scan2<<<NSB, 1024>>>();                                      // 1
    k_fill_prep<<<(NPREP + TB - 1) / TB, TB>>>(src, dst, feat);    // 2

    k_fused<<<NT, 1024, FSMEM>>>(0, 0, b + 0 * DD, nullptr, 1);    // 3 <-- profiled
    k_fused<<<NT, 1024, FSMEM>>>(1, 1, b + 1 * DD, nullptr, 2);
    k_fused<<<NT, 1024, FSMEM>>>(2, 2, b + 2 * DD, nullptr, 1);
    k_fused<<<NT, 1024, FSMEM>>>(1, 3, b + 3 * DD, out, 0);
}

// round 16
// speedup vs baseline: 1.0891x; 1.0891x over previous
#include <cuda_runtime.h>
#include <cuda_bf16.h>
#include <cuda_fp16.h>

#define NN 50000
#define NE 600000
#define DD 128
#define NT 391            // 128-row tiles covering 50048 rows
#define LDA 136           // padded smem row (bf16 units): 272B, conflict-free ldmatrix
#define NSB 49            // scan blocks: 49 * 1024 >= NN
#define NPREP (NN * DD / 4)   // 1.6M quads

// ---------------- scratch (device globals; no allocation allowed) ----------------
// counters zero at module load; re-zeroed inside k_fill_prep each call
__device__ int   g_out_cnt[NN];
__device__ int   g_in_cnt[NN];
__device__ int   g_row_off[NN + 1];
__device__ int   g_cursor[NN];
__device__ int   g_csr_src[NE];
__device__ float g_src_norm[NN];
__device__ float g_dst_norm[NN];
// fp16 feature storage, prescaled by src_norm
__device__ __align__(16) __half g_f16[NN * DD];   // layer-0 input
__device__ __align__(16) __half g_p0[NN * DD];    // ping-pong prescaled h
__device__ __align__(16) __half g_p1[NN * DD];
// bf16 split of W (k x n row-major), per layer
__device__ __align__(16) unsigned short g_wh16[4 * DD * DD];
__device__ __align__(16) unsigned short g_wl16[4 * DD * DD];

// ---------------- PTX helpers (base sm_100 compatible only!) ----------------
__device__ __forceinline__ unsigned s2u(const void* p) {
    unsigned r;
    asm("{ .reg .u64 t; cvta.to.shared.u64 t, %1; cvt.u32.u64 %0, t; }" : "=r"(r) : "l"(p));
    return r;
}
#define LDSM_X4(r, a)                                                         \
    asm volatile("ldmatrix.sync.aligned.m8n8.x4.shared.b16 {%0,%1,%2,%3}, [%4];" \
        : "=r"((r)[0]), "=r"((r)[1]), "=r"((r)[2]), "=r"((r)[3]) : "r"(a))
#define LDSM_X4T(r, a)                                                        \
    asm volatile("ldmatrix.sync.aligned.m8n8.x4.trans.shared.b16 {%0,%1,%2,%3}, [%4];" \
        : "=r"((r)[0]), "=r"((r)[1]), "=r"((r)[2]), "=r"((r)[3]) : "r"(a))
#define MMA16816(c, a, b0_, b1_)                                              \
    asm volatile("mma.sync.aligned.m16n8k16.row.col.f32.bf16.bf16.f32 "       \
        "{%0,%1,%2,%3},{%4,%5,%6,%7},{%8,%9},{%0,%1,%2,%3};"                  \
        : "+f"((c)[0]), "+f"((c)[1]), "+f"((c)[2]), "+f"((c)[3])              \
        : "r"((a)[0]), "r"((a)[1]), "r"((a)[2]), "r"((a)[3]), "r"(b0_), "r"(b1_))

// add 4 halves (uint2) into float4 accumulator
__device__ __forceinline__ void acc_h4(float4& A, uint2 u) {
    float2 a = __half22float2(*(__half2*)&u.x);
    float2 b = __half22float2(*(__half2*)&u.y);
    A.x += a.x; A.y += a.y; A.z += b.x; A.w += b.y;
}

// ---------------- launch 0: degree count + W split (fused) ----------------
__global__ void k_count_w(const int* __restrict__ src, const int* __restrict__ dst,
                          const float* __restrict__ W) {
    int e = blockIdx.x * blockDim.x + threadIdx.x;
    if (e < NE) {
        atomicAdd(&g_out_cnt[src[e]], 1);
        atomicAdd(&g_in_cnt[dst[e]], 1);
    }
    if (e < 4 * DD * DD) {
        float v = __ldg(W + e);
        __nv_bfloat16 hi = __float2bfloat16(v);
        float lo = v - __bfloat162float(hi);
        g_wh16[e] = __bfloat16_as_ushort(hi);
        g_wl16[e] = __bfloat16_as_ushort(__float2bfloat16(lo));
    }
}

// ---------------- launch 1: one-kernel scan (self-computed base) + norms ----------
__global__ __launch_bounds__(1024) void k_scan2() {
    __shared__ int sd[1024];
    __shared__ int sbase;
    int t = threadIdx.x, b = blockIdx.x;
    int i = b * 1024 + t;
    int incnt = (i < NN) ? g_in_cnt[i] : 0;
    int part = 0;
    for (int k = t; k < b * 1024; k += 1024) part += g_in_cnt[k];
    sd[t] = part;
    __syncthreads();
#pragma unroll
    for (int s = 512; s > 0; s >>= 1) {
        if (t < s) sd[t] += sd[t + s];
        __syncthreads();
    }
    if (t == 0) sbase = sd[0];
    __syncthreads();
    int base = sbase;
    __syncthreads();
    sd[t] = incnt;
    __syncthreads();
#pragma unroll
    for (int off = 1; off < 1024; off <<= 1) {
        int v = (t >= off) ? sd[t - off] : 0;
        __syncthreads();
        sd[t] += v;
        __syncthreads();
    }
    int excl = sd[t] - incnt;
    if (i < NN) {
        int o = base + excl;
        g_row_off[i] = o;
        g_cursor[i]  = o;
        g_src_norm[i] = rsqrtf((float)max(g_out_cnt[i], 1));
        g_dst_norm[i] = rsqrtf((float)max(incnt, 1));
    }
    if (b == NSB - 1 && t == 1023) g_row_off[NN] = base + sd[1023];
}

// ---------------- launch 2: CSR fill + counter re-zero + feat prescale->fp16 -----
__global__ void k_fill_prep(const int* __restrict__ src, const int* __restrict__ dst,
                            const float* __restrict__ feat) {
    int e = blockIdx.x * blockDim.x + threadIdx.x;   // grid sized for NPREP
    if (e < NE) {
        int d = dst[e];
        int p = atomicAdd(&g_cursor[d], 1);
        g_csr_src[p] = src[e];
    }
    if (e < NN) { g_out_cnt[e] = 0; g_in_cnt[e] = 0; }
    if (e < NPREP) {
        int row = e >> 5;
        float sn = __ldg(&g_src_norm[row]);
        float4 v = __ldg((const float4*)feat + e);
        __half2 a = __floats2half2_rn(v.x * sn, v.y * sn);
        __half2 b = __floats2half2_rn(v.z * sn, v.w * sn);
        uint2 u; u.x = *(unsigned*)&a; u.y = *(unsigned*)&b;
        *((uint2*)g_f16 + e) = u;
    }
}

// ---------------- fused aggregate + GEMM: warp-wide idx fetch + shfl broadcast ----
// CTA t: nodes [t*128, t*128+128). 1024 threads (32 warps), 1 CTA/SM.
// Phase 1: warp w sums fp16 rows for nodes w*4..w*4+3. For each node, ALL lanes
//          load up to 32 CSR indices in one coalesced LDG; indices broadcast via
//          shfl (ALU, not memory). Row loads issue back-to-back, 4 indep accs.
// Phase 2: 32 warps mma, warp tile 32m x 16n, 3-term bf16 split (unchanged).
#define FSMEM (4 * DD * LDA * 2)

__global__ __launch_bounds__(1024, 1) void k_fused(
        int sel, int layer, const float* __restrict__ bias,
        float* __restrict__ ext_out, int out_sel) {
    extern __shared__ unsigned short smx[];
    unsigned short* sWh = smx;
    unsigned short* sWl = smx + DD * LDA;
    unsigned short* sAh = smx + 2 * DD * LDA;
    unsigned short* sAl = smx + 3 * DD * LDA;

    int tid = threadIdx.x, lane = tid & 31, w = tid >> 5;
    int t = blockIdx.x;
    const uint2* h2 = (const uint2*)(sel == 0 ? g_f16 : (sel == 1 ? g_p0 : g_p1));

    // stage W (1024 threads x 2 uint4 each per array)
    {
        const uint4* w_h = (const uint4*)(g_wh16 + layer * DD * DD);
        const uint4* w_l = (const uint4*)(g_wl16 + layer * DD * DD);
#pragma unroll
        for (int i = 0; i < 2; i++) {
            int li = tid + i * 1024;
            int r = li >> 4, c = li & 15;
            int d = r * LDA + c * 8;
            *(uint4*)&sWh[d] = w_h[li];
            *(uint4*)&sWl[d] = w_l[li];
        }
    }

    // ---------------- phase 1: sum fp16 rows, 4 nodes per warp -------------------
#pragma unroll
    for (int q = 0; q < 4; q++) {
        int r = w * 4 + q;              // local row 0..127
        int gw = t * DD + r;            // warp-uniform
        float4 acc = make_float4(0.f, 0.f, 0.f, 0.f);
        if (gw < NN) {
            int beg = __ldg(&g_row_off[gw]), end = __ldg(&g_row_off[gw + 1]);
            float4 A0 = make_float4(0.f, 0.f, 0.f, 0.f);
            float4 A1 = make_float4(0.f, 0.f, 0.f, 0.f);
            float4 A2 = make_float4(0.f, 0.f, 0.f, 0.f);
            float4 A3 = make_float4(0.f, 0.f, 0.f, 0.f);
            for (int base = beg; base < end; base += 32) {
                int pos = base + lane;
                int sidx = (pos < end) ? __ldg(&g_csr_src[pos]) : 0;
                int cnt = min(32, end - base);
                int k = 0;
                for (; k + 8 <= cnt; k += 8) {
                    int s0 = __shfl_sync(0xFFFFFFFFu, sidx, k + 0);
                    int s1 = __shfl_sync(0xFFFFFFFFu, sidx, k + 1);
                    int s2 = __shfl_sync(0xFFFFFFFFu, sidx, k + 2);
                    int s3 = __shfl_sync(0xFFFFFFFFu, sidx, k + 3);
                    int s4 = __shfl_sync(0xFFFFFFFFu, sidx, k + 4);
                    int s5 = __shfl_sync(0xFFFFFFFFu, sidx, k + 5);
                    int s6 = __shfl_sync(0xFFFFFFFFu, sidx, k + 6);
                    int s7 = __shfl_sync(0xFFFFFFFFu, sidx, k + 7);
                    uint2 u0 = __ldg(&h2[s0 * 32 + lane]);
                    uint2 u1 = __ldg(&h2[s1 * 32 + lane]);
                    uint2 u2 = __ldg(&h2[s2 * 32 + lane]);
                    uint2 u3 = __ldg(&h2[s3 * 32 + lane]);
                    uint2 u4 = __ldg(&h2[s4 * 32 + lane]);
                    uint2 u5 = __ldg(&h2[s5 * 32 + lane]);
                    uint2 u6 = __ldg(&h2[s6 * 32 + lane]);
                    uint2 u7 = __ldg(&h2[s7 * 32 + lane]);
                    acc_h4(A0, u0); acc_h4(A1, u1); acc_h4(A2, u2); acc_h4(A3, u3);
                    acc_h4(A0, u4); acc_h4(A1, u5); acc_h4(A2, u6); acc_h4(A3, u7);
                }
                for (; k + 4 <= cnt; k += 4) {
                    int s0 = __shfl_sync(0xFFFFFFFFu, sidx, k + 0);
                    int s1 = __shfl_sync(0xFFFFFFFFu, sidx, k + 1);
                    int s2 = __shfl_sync(0xFFFFFFFFu, sidx, k + 2);
                    int s3 = __shfl_sync(0xFFFFFFFFu, sidx, k + 3);
                    uint2 u0 = __ldg(&h2[s0 * 32 + lane]);
                    uint2 u1 = __ldg(&h2[s1 * 32 + lane]);
                    uint2 u2 = __ldg(&h2[s2 * 32 + lane]);
                    uint2 u3 = __ldg(&h2[s3 * 32 + lane]);
                    acc_h4(A0, u0); acc_h4(A1, u1); acc_h4(A2, u2); acc_h4(A3, u3);
                }
                if (k + 2 <= cnt) {
                    int s0 = __shfl_sync(0xFFFFFFFFu, sidx, k + 0);
                    int s1 = __shfl_sync(0xFFFFFFFFu, sidx, k + 1);
                    uint2 u0 = __ldg(&h2[s0 * 32 + lane]);
                    uint2 u1 = __ldg(&h2[s1 * 32 + lane]);
                    acc_h4(A0, u0); acc_h4(A1, u1);
                    k += 2;
                }
                if (k < cnt) {
                    int s0 = __shfl_sync(0xFFFFFFFFu, sidx, k);
                    acc_h4(A0, __ldg(&h2[s0 * 32 + lane]));
                }
            }
            float dn = __ldg(&g_dst_norm[gw]);
            acc.x = ((A0.x + A1.x) + (A2.x + A3.x)) * dn;
            acc.y = ((A0.y + A1.y) + (A2.y + A3.y)) * dn;
            acc.z = ((A0.z + A1.z) + (A2.z + A3.z)) * dn;
            acc.w = ((A0.w + A1.w) + (A2.w + A3.w)) * dn;
        }
        // split to bf16 hi/lo, store to smem in ldmatrix layout
        __nv_bfloat16 hx = __float2bfloat16(acc.x), hy = __float2bfloat16(acc.y);
        __nv_bfloat16 hz = __float2bfloat16(acc.z), hw = __float2bfloat16(acc.w);
        ushort4 vh, vl;
        vh.x = __bfloat16_as_ushort(hx); vh.y = __bfloat16_as_ushort(hy);
        vh.z = __bfloat16_as_ushort(hz); vh.w = __bfloat16_as_ushort(hw);
        vl.x = __bfloat16_as_ushort(__float2bfloat16(acc.x - __bfloat162float(hx)));
        vl.y = __bfloat16_as_ushort(__float2bfloat16(acc.y - __bfloat162float(hy)));
        vl.z = __bfloat16_as_ushort(__float2bfloat16(acc.z - __bfloat162float(hz)));
        vl.w = __bfloat16_as_ushort(__float2bfloat16(acc.w - __bfloat162float(hw)));
        *(ushort4*)&sAh[r * LDA + lane * 4] = vh;
        *(ushort4*)&sAl[r * LDA + lane * 4] = vl;
    }
    __syncthreads();

    // ---------------- phase 2: 3-term mma, warp tile 32m x 16n ----------------
    int mw = w & 3, nw = w >> 2;     // 4 m-groups x 8 n-groups

    float acc2[2][2][4];
#pragma unroll
    for (int mt = 0; mt < 2; mt++)
#pragma unroll
        for (int nt = 0; nt < 2; nt++)
#pragma unroll
            for (int q = 0; q < 4; q++) acc2[mt][nt][q] = 0.f;

    unsigned aH[2], aL[2];
#pragma unroll
    for (int mt = 0; mt < 2; mt++) {
        int r = mw * 32 + mt * 16 + (lane & 15);
        aH[mt] = s2u(&sAh[r * LDA + (lane >> 4) * 8]);
        aL[mt] = s2u(&sAl[r * LDA + (lane >> 4) * 8]);
    }
    unsigned bB = (lane < 16) ? s2u(&sWh[(lane & 15) * LDA + nw * 16])
                              : s2u(&sWl[(lane & 15) * LDA + nw * 16]);

#pragma unroll
    for (int ks = 0; ks < 8; ks++) {
        unsigned ah[2][4], al[2][4];
#pragma unroll
        for (int mt = 0; mt < 2; mt++) {
            LDSM_X4(ah[mt], aH[mt] + ks * 32);
            LDSM_X4(al[mt], aL[mt] + ks * 32);
        }
#pragma unroll
        for (int nt = 0; nt < 2; nt++) {
            unsigned b[4];                 // b[0..1]=Wh frag, b[2..3]=Wl frag
            LDSM_X4T(b, bB + ks * 16 * LDA * 2 + nt * 16);
#pragma unroll
            for (int mt = 0; mt < 2; mt++) {
                MMA16816(acc2[mt][nt], ah[mt], b[0], b[1]);
                MMA16816(acc2[mt][nt], ah[mt], b[2], b[3]);
                MMA16816(acc2[mt][nt], al[mt], b[0], b[1]);
            }
        }
    }

    // epilogue: layers 0-2 -> fp16 prescaled by src_norm; final -> fp32 ext
    __half* outh = (out_sel == 1) ? g_p0 : g_p1;
#pragma unroll
    for (int mt = 0; mt < 2; mt++) {
        int r0 = t * DD + mw * 32 + mt * 16 + (lane >> 2);
        int r1 = r0 + 8;
        float sn0 = 1.f, sn1 = 1.f;
        if (out_sel != 0) {
            if (r0 < NN) sn0 = __ldg(&g_src_norm[r0]);
            if (r1 < NN) sn1 = __ldg(&g_src_norm[r1]);
        }
#pragma unroll
        for (int nt = 0; nt < 2; nt++) {
            int col = nw * 16 + nt * 8 + (lane & 3) * 2;
            float2 bb = *(const float2*)&bias[col];
            if (out_sel == 0) {
                if (r0 < NN) {
                    float2 v; v.x = acc2[mt][nt][0] + bb.x; v.y = acc2[mt][nt][1] + bb.y;
                    *(float2*)&ext_out[(size_t)r0 * DD + col] = v;
                }
                if (r1 < NN) {
                    float2 v; v.x = acc2[mt][nt][2] + bb.x; v.y = acc2[mt][nt][3] + bb.y;
                    *(float2*)&ext_out[(size_t)r1 * DD + col] = v;
                }
            } else {
                if (r0 < NN) {
                    __half2 v = __floats2half2_rn((acc2[mt][nt][0] + bb.x) * sn0,
                                                  (acc2[mt][nt][1] + bb.y) * sn0);
                    *(__half2*)&outh[(size_t)r0 * DD + col] = v;
                }
                if (r1 < NN) {
                    __half2 v = __floats2half2_rn((acc2[mt][nt][2] + bb.x) * sn1,
                                                  (acc2[mt][nt][3] + bb.y) * sn1);
                    *(__half2*)&outh[(size_t)r1 * DD + col] = v;
                }
            }
        }
    }
}

// ---------------- launch ----------------
extern "C" void kernel_launch(void* const* d_in, const int* in_sizes, int n_in,
                              void* d_out, int out_size) {
    const float* feat = (const float*)d_in[0];
    const int*   src  = (const int*)d_in[1];
    const int*   dst  = (const int*)d_in[2];
    const float* W    = (const float*)d_in[3];
    const float* b    = (const float*)d_in[4];
    float* out = (float*)d_out;

    cudaFuncSetAttribute(k_fused, cudaFuncAttributeMaxDynamicSharedMemorySize, FSMEM);

    const int TB = 256;
    k_count_w<<<(NE + TB - 1) / TB, TB>>>(src, dst, W);            // 0
    k_scan2<<<NSB, 1024>>>();                                      // 1
    k_fill_prep<<<(NPREP + TB - 1) / TB, TB>>>(src, dst, feat);    // 2

    k_fused<<<NT, 1024, FSMEM>>>(0, 0, b + 0 * DD, nullptr, 1);    // 3 <-- profiled
    k_fused<<<NT, 1024, FSMEM>>>(1, 1, b + 1 * DD, nullptr, 2);
    k_fused<<<NT, 1024, FSMEM>>>(2, 2, b + 2 * DD, nullptr, 1);
    k_fused<<<NT, 1024, FSMEM>>>(1, 3, b + 3 * DD, out, 0);
}

// round 17
// speedup vs baseline: 1.0958x; 1.0061x over previous
#include <cuda_runtime.h>
#include <cuda_bf16.h>
#include <cuda_fp16.h>

#define NN 50000
#define NE 600000
#define DD 128
#define NT 391            // 128-row tiles covering 50048 rows
#define LDA 136           // padded smem row (bf16 units): 272B, conflict-free ldmatrix
#define NSB 49            // scan blocks: 49 * 1024 >= NN
#define NPREP (NN * DD / 4)   // 1.6M quads

// ---------------- scratch (device globals; no allocation allowed) ----------------
// counters zero at module load; re-zeroed inside k_fill_prep each call
__device__ int   g_out_cnt[NN];
__device__ int   g_in_cnt[NN];
__device__ int   g_row_off[NN + 1];
__device__ int   g_cursor[NN];
__device__ int   g_csr_src[NE];
__device__ float g_src_norm[NN];
__device__ float g_dst_norm[NN];
// fp16 feature storage, prescaled by src_norm
__device__ __align__(16) __half g_f16[NN * DD];   // layer-0 input
__device__ __align__(16) __half g_p0[NN * DD];    // ping-pong prescaled h
__device__ __align__(16) __half g_p1[NN * DD];
// bf16 split of W (k x n row-major), per layer
__device__ __align__(16) unsigned short g_wh16[4 * DD * DD];
__device__ __align__(16) unsigned short g_wl16[4 * DD * DD];

// ---------------- PTX helpers (base sm_100 compatible only!) ----------------
__device__ __forceinline__ unsigned s2u(const void* p) {
    unsigned r;
    asm("{ .reg .u64 t; cvta.to.shared.u64 t, %1; cvt.u32.u64 %0, t; }" : "=r"(r) : "l"(p));
    return r;
}
#define LDSM_X4(r, a)                                                         \
    asm volatile("ldmatrix.sync.aligned.m8n8.x4.shared.b16 {%0,%1,%2,%3}, [%4];" \
        : "=r"((r)[0]), "=r"((r)[1]), "=r"((r)[2]), "=r"((r)[3]) : "r"(a))
#define LDSM_X4T(r, a)                                                        \
    asm volatile("ldmatrix.sync.aligned.m8n8.x4.trans.shared.b16 {%0,%1,%2,%3}, [%4];" \
        : "=r"((r)[0]), "=r"((r)[1]), "=r"((r)[2]), "=r"((r)[3]) : "r"(a))
#define MMA16816(c, a, b0_, b1_)                                              \
    asm volatile("mma.sync.aligned.m16n8k16.row.col.f32.bf16.bf16.f32 "       \
        "{%0,%1,%2,%3},{%4,%5,%6,%7},{%8,%9},{%0,%1,%2,%3};"                  \
        : "+f"((c)[0]), "+f"((c)[1]), "+f"((c)[2]), "+f"((c)[3])              \
        : "r"((a)[0]), "r"((a)[1]), "r"((a)[2]), "r"((a)[3]), "r"(b0_), "r"(b1_))

// add 4 halves (uint2) into float4 accumulator
__device__ __forceinline__ void acc_h4(float4& A, uint2 u) {
    float2 a = __half22float2(*(__half2*)&u.x);
    float2 b = __half22float2(*(__half2*)&u.y);
    A.x += a.x; A.y += a.y; A.z += b.x; A.w += b.y;
}

// ---------------- launch 0: degree count + W split (fused) ----------------
__global__ void k_count_w(const int* __restrict__ src, const int* __restrict__ dst,
                          const float* __restrict__ W) {
    int e = blockIdx.x * blockDim.x + threadIdx.x;
    if (e < NE) {
        atomicAdd(&g_out_cnt[src[e]], 1);
        atomicAdd(&g_in_cnt[dst[e]], 1);
    }
    if (e < 4 * DD * DD) {
        float v = __ldg(W + e);
        __nv_bfloat16 hi = __float2bfloat16(v);
        float lo = v - __bfloat162float(hi);
        g_wh16[e] = __bfloat16_as_ushort(hi);
        g_wl16[e] = __bfloat16_as_ushort(__float2bfloat16(lo));
    }
}

// ---------------- launch 1: one-kernel scan (self-computed base) + norms ----------
__global__ __launch_bounds__(1024) void k_scan2() {
    __shared__ int sd[1024];
    __shared__ int sbase;
    int t = threadIdx.x, b = blockIdx.x;
    int i = b * 1024 + t;
    int incnt = (i < NN) ? g_in_cnt[i] : 0;
    int part = 0;
    for (int k = t; k < b * 1024; k += 1024) part += g_in_cnt[k];
    sd[t] = part;
    __syncthreads();
#pragma unroll
    for (int s = 512; s > 0; s >>= 1) {
        if (t < s) sd[t] += sd[t + s];
        __syncthreads();
    }
    if (t == 0) sbase = sd[0];
    __syncthreads();
    int base = sbase;
    __syncthreads();
    sd[t] = incnt;
    __syncthreads();
#pragma unroll
    for (int off = 1; off < 1024; off <<= 1) {
        int v = (t >= off) ? sd[t - off] : 0;
        __syncthreads();
        sd[t] += v;
        __syncthreads();
    }
    int excl = sd[t] - incnt;
    if (i < NN) {
        int o = base + excl;
        g_row_off[i] = o;
        g_cursor[i]  = o;
        g_src_norm[i] = rsqrtf((float)max(g_out_cnt[i], 1));
        g_dst_norm[i] = rsqrtf((float)max(incnt, 1));
    }
    if (b == NSB - 1 && t == 1023) g_row_off[NN] = base + sd[1023];
}

// ---------------- launch 2: CSR fill + counter re-zero + feat prescale->fp16 -----
__global__ void k_fill_prep(const int* __restrict__ src, const int* __restrict__ dst,
                            const float* __restrict__ feat) {
    int e = blockIdx.x * blockDim.x + threadIdx.x;   // grid sized for NPREP
    if (e < NE) {
        int d = dst[e];
        int p = atomicAdd(&g_cursor[d], 1);
        g_csr_src[p] = src[e];
    }
    if (e < NN) { g_out_cnt[e] = 0; g_in_cnt[e] = 0; }
    if (e < NPREP) {
        int row = e >> 5;
        float sn = __ldg(&g_src_norm[row]);
        float4 v = __ldg((const float4*)feat + e);
        __half2 a = __floats2half2_rn(v.x * sn, v.y * sn);
        __half2 b = __floats2half2_rn(v.z * sn, v.w * sn);
        uint2 u; u.x = *(unsigned*)&a; u.y = *(unsigned*)&b;
        *((uint2*)g_f16 + e) = u;
    }
}

// ---------------- fused aggregate + GEMM: batched-prelude gather -----------------
// CTA t: nodes [t*128, t*128+128). 1024 threads (32 warps), 1 CTA/SM.
// Phase 1: warp w sums fp16 rows for nodes w*4..w*4+3.
//   * ONE coalesced LDG fetches the 5 row_off bounds (lanes 0-4) + shfl.
//   * ALL 4 nodes' first index batches are issued back-to-back (4 LDGs in
//     flight) before any node processes -> one exposed idx latency, not four.
//   * Per node: shfl-broadcast ladder, 4 independent accumulators (validated).
// Phase 2: 32 warps mma, warp tile 32m x 16n, 3-term bf16 split (unchanged).
#define FSMEM (4 * DD * LDA * 2)

__global__ __launch_bounds__(1024, 1) void k_fused(
        int sel, int layer, const float* __restrict__ bias,
        float* __restrict__ ext_out, int out_sel) {
    extern __shared__ unsigned short smx[];
    unsigned short* sWh = smx;
    unsigned short* sWl = smx + DD * LDA;
    unsigned short* sAh = smx + 2 * DD * LDA;
    unsigned short* sAl = smx + 3 * DD * LDA;

    int tid = threadIdx.x, lane = tid & 31, w = tid >> 5;
    int t = blockIdx.x;
    const uint2* h2 = (const uint2*)(sel == 0 ? g_f16 : (sel == 1 ? g_p0 : g_p1));

    // stage W (1024 threads x 2 uint4 each per array)
    {
        const uint4* w_h = (const uint4*)(g_wh16 + layer * DD * DD);
        const uint4* w_l = (const uint4*)(g_wl16 + layer * DD * DD);
#pragma unroll
        for (int i = 0; i < 2; i++) {
            int li = tid + i * 1024;
            int r = li >> 4, c = li & 15;
            int d = r * LDA + c * 8;
            *(uint4*)&sWh[d] = w_h[li];
            *(uint4*)&sWl[d] = w_l[li];
        }
    }

    // ---------------- phase 1: batched prelude, then per-node shfl ladder --------
    {
        int r0w = w * 4;
        int gw0 = t * DD + r0w;
        // one LDG: row_off[gw0 .. gw0+4] via lanes 0..4 (clamped), then shfl
        int b5 = __ldg(&g_row_off[min(gw0 + ((lane < 5) ? lane : 4), NN)]);
        // issue ALL 4 first index batches back-to-back
        int sidx4[4];
#pragma unroll
        for (int q = 0; q < 4; q++) {
            int beg = __shfl_sync(0xFFFFFFFFu, b5, q);
            int end = __shfl_sync(0xFFFFFFFFu, b5, q + 1);
            int gwq = gw0 + q;
            int pos = beg + lane;
            sidx4[q] = (gwq < NN && pos < end) ? __ldg(&g_csr_src[pos]) : 0;
        }
#pragma unroll
        for (int q = 0; q < 4; q++) {
            int r = r0w + q;
            int gw = gw0 + q;
            float4 acc = make_float4(0.f, 0.f, 0.f, 0.f);
            if (gw < NN) {
                int beg = __shfl_sync(0xFFFFFFFFu, b5, q);
                int end = __shfl_sync(0xFFFFFFFFu, b5, q + 1);
                float4 A0 = make_float4(0.f, 0.f, 0.f, 0.f);
                float4 A1 = make_float4(0.f, 0.f, 0.f, 0.f);
                float4 A2 = make_float4(0.f, 0.f, 0.f, 0.f);
                float4 A3 = make_float4(0.f, 0.f, 0.f, 0.f);
                for (int base = beg; base < end; base += 32) {
                    int sidx;
                    if (base == beg) {
                        sidx = sidx4[q];                    // prefetched
                    } else {
                        int pos = base + lane;
                        sidx = (pos < end) ? __ldg(&g_csr_src[pos]) : 0;
                    }
                    int cnt = min(32, end - base);
                    int k = 0;
                    for (; k + 8 <= cnt; k += 8) {
                        int s0 = __shfl_sync(0xFFFFFFFFu, sidx, k + 0);
                        int s1 = __shfl_sync(0xFFFFFFFFu, sidx, k + 1);
                        int s2 = __shfl_sync(0xFFFFFFFFu, sidx, k + 2);
                        int s3 = __shfl_sync(0xFFFFFFFFu, sidx, k + 3);
                        int s4 = __shfl_sync(0xFFFFFFFFu, sidx, k + 4);
                        int s5 = __shfl_sync(0xFFFFFFFFu, sidx, k + 5);
                        int s6 = __shfl_sync(0xFFFFFFFFu, sidx, k + 6);
                        int s7 = __shfl_sync(0xFFFFFFFFu, sidx, k + 7);
                        uint2 u0 = __ldg(&h2[s0 * 32 + lane]);
                        uint2 u1 = __ldg(&h2[s1 * 32 + lane]);
                        uint2 u2 = __ldg(&h2[s2 * 32 + lane]);
                        uint2 u3 = __ldg(&h2[s3 * 32 + lane]);
                        uint2 u4 = __ldg(&h2[s4 * 32 + lane]);
                        uint2 u5 = __ldg(&h2[s5 * 32 + lane]);
                        uint2 u6 = __ldg(&h2[s6 * 32 + lane]);
                        uint2 u7 = __ldg(&h2[s7 * 32 + lane]);
                        acc_h4(A0, u0); acc_h4(A1, u1); acc_h4(A2, u2); acc_h4(A3, u3);
                        acc_h4(A0, u4); acc_h4(A1, u5); acc_h4(A2, u6); acc_h4(A3, u7);
                    }
                    for (; k + 4 <= cnt; k += 4) {
                        int s0 = __shfl_sync(0xFFFFFFFFu, sidx, k + 0);
                        int s1 = __shfl_sync(0xFFFFFFFFu, sidx, k + 1);
                        int s2 = __shfl_sync(0xFFFFFFFFu, sidx, k + 2);
                        int s3 = __shfl_sync(0xFFFFFFFFu, sidx, k + 3);
                        uint2 u0 = __ldg(&h2[s0 * 32 + lane]);
                        uint2 u1 = __ldg(&h2[s1 * 32 + lane]);
                        uint2 u2 = __ldg(&h2[s2 * 32 + lane]);
                        uint2 u3 = __ldg(&h2[s3 * 32 + lane]);
                        acc_h4(A0, u0); acc_h4(A1, u1); acc_h4(A2, u2); acc_h4(A3, u3);
                    }
                    if (k + 2 <= cnt) {
                        int s0 = __shfl_sync(0xFFFFFFFFu, sidx, k + 0);
                        int s1 = __shfl_sync(0xFFFFFFFFu, sidx, k + 1);
                        uint2 u0 = __ldg(&h2[s0 * 32 + lane]);
                        uint2 u1 = __ldg(&h2[s1 * 32 + lane]);
                        acc_h4(A0, u0); acc_h4(A1, u1);
                        k += 2;
                    }
                    if (k < cnt) {
                        int s0 = __shfl_sync(0xFFFFFFFFu, sidx, k);
                        acc_h4(A0, __ldg(&h2[s0 * 32 + lane]));
                    }
                }
                float dn = __ldg(&g_dst_norm[gw]);
                acc.x = ((A0.x + A1.x) + (A2.x + A3.x)) * dn;
                acc.y = ((A0.y + A1.y) + (A2.y + A3.y)) * dn;
                acc.z = ((A0.z + A1.z) + (A2.z + A3.z)) * dn;
                acc.w = ((A0.w + A1.w) + (A2.w + A3.w)) * dn;
            }
            // split to bf16 hi/lo, store to smem in ldmatrix layout
            __nv_bfloat16 hx = __float2bfloat16(acc.x), hy = __float2bfloat16(acc.y);
            __nv_bfloat16 hz = __float2bfloat16(acc.z), hw = __float2bfloat16(acc.w);
            ushort4 vh, vl;
            vh.x = __bfloat16_as_ushort(hx); vh.y = __bfloat16_as_ushort(hy);
            vh.z = __bfloat16_as_ushort(hz); vh.w = __bfloat16_as_ushort(hw);
            vl.x = __bfloat16_as_ushort(__float2bfloat16(acc.x - __bfloat162float(hx)));
            vl.y = __bfloat16_as_ushort(__float2bfloat16(acc.y - __bfloat162float(hy)));
            vl.z = __bfloat16_as_ushort(__float2bfloat16(acc.z - __bfloat162float(hz)));
            vl.w = __bfloat16_as_ushort(__float2bfloat16(acc.w - __bfloat162float(hw)));
            *(ushort4*)&sAh[r * LDA + lane * 4] = vh;
            *(ushort4*)&sAl[r * LDA + lane * 4] = vl;
        }
    }
    __syncthreads();

    // ---------------- phase 2: 3-term mma, warp tile 32m x 16n ----------------
    int mw = w & 3, nw = w >> 2;     // 4 m-groups x 8 n-groups

    float acc2[2][2][4];
#pragma unroll
    for (int mt = 0; mt < 2; mt++)
#pragma unroll
        for (int nt = 0; nt < 2; nt++)
#pragma unroll
            for (int q = 0; q < 4; q++) acc2[mt][nt][q] = 0.f;

    unsigned aH[2], aL[2];
#pragma unroll
    for (int mt = 0; mt < 2; mt++) {
        int r = mw * 32 + mt * 16 + (lane & 15);
        aH[mt] = s2u(&sAh[r * LDA + (lane >> 4) * 8]);
        aL[mt] = s2u(&sAl[r * LDA + (lane >> 4) * 8]);
    }
    unsigned bB = (lane < 16) ? s2u(&sWh[(lane & 15) * LDA + nw * 16])
                              : s2u(&sWl[(lane & 15) * LDA + nw * 16]);

#pragma unroll
    for (int ks = 0; ks < 8; ks++) {
        unsigned ah[2][4], al[2][4];
#pragma unroll
        for (int mt = 0; mt < 2; mt++) {
            LDSM_X4(ah[mt], aH[mt] + ks * 32);
            LDSM_X4(al[mt], aL[mt] + ks * 32);
        }
#pragma unroll
        for (int nt = 0; nt < 2; nt++) {
            unsigned b[4];                 // b[0..1]=Wh frag, b[2..3]=Wl frag
            LDSM_X4T(b, bB + ks * 16 * LDA * 2 + nt * 16);
#pragma unroll
            for (int mt = 0; mt < 2; mt++) {
                MMA16816(acc2[mt][nt], ah[mt], b[0], b[1]);
                MMA16816(acc2[mt][nt], ah[mt], b[2], b[3]);
                MMA16816(acc2[mt][nt], al[mt], b[0], b[1]);
            }
        }
    }

    // epilogue: layers 0-2 -> fp16 prescaled by src_norm; final -> fp32 ext
    __half* outh = (out_sel == 1) ? g_p0 : g_p1;
#pragma unroll
    for (int mt = 0; mt < 2; mt++) {
        int r0 = t * DD + mw * 32 + mt * 16 + (lane >> 2);
        int r1 = r0 + 8;
        float sn0 = 1.f, sn1 = 1.f;
        if (out_sel != 0) {
            if (r0 < NN) sn0 = __ldg(&g_src_norm[r0]);
            if (r1 < NN) sn1 = __ldg(&g_src_norm[r1]);
        }
#pragma unroll
        for (int nt = 0; nt < 2; nt++) {
            int col = nw * 16 + nt * 8 + (lane & 3) * 2;
            float2 bb = *(const float2*)&bias[col];
            if (out_sel == 0) {
                if (r0 < NN) {
                    float2 v; v.x = acc2[mt][nt][0] + bb.x; v.y = acc2[mt][nt][1] + bb.y;
                    *(float2*)&ext_out[(size_t)r0 * DD + col] = v;
                }
                if (r1 < NN) {
                    float2 v; v.x = acc2[mt][nt][2] + bb.x; v.y = acc2[mt][nt][3] + bb.y;
                    *(float2*)&ext_out[(size_t)r1 * DD + col] = v;
                }
            } else {
                if (r0 < NN) {
                    __half2 v = __floats2half2_rn((acc2[mt][nt][0] + bb.x) * sn0,
                                                  (acc2[mt][nt][1] + bb.y) * sn0);
                    *(__half2*)&outh[(size_t)r0 * DD + col] = v;
                }
                if (r1 < NN) {
                    __half2 v = __floats2half2_rn((acc2[mt][nt][2] + bb.x) * sn1,
                                                  (acc2[mt][nt][3] + bb.y) * sn1);
                    *(__half2*)&outh[(size_t)r1 * DD + col] = v;
                }
            }
        }
    }
}

// ---------------- launch ----------------
extern "C" void kernel_launch(void* const* d_in, const int* in_sizes, int n_in,
                              void* d_out, int out_size) {
    const float* feat = (const float*)d_in[0];
    const int*   src  = (const int*)d_in[1];
    const int*   dst  = (const int*)d_in[2];
    const float* W    = (const float*)d_in[3];
    const float* b    = (const float*)d_in[4];
    float* out = (float*)d_out;

    cudaFuncSetAttribute(k_fused, cudaFuncAttributeMaxDynamicSharedMemorySize, FSMEM);

    const int TB = 256;
    k_count_w<<<(NE + TB - 1) / TB, TB>>>(src, dst, W);            // 0
    k_scan2<<<NSB, 1024>>>();                                      // 1
    k_fill_prep<<<(NPREP + TB - 1) / TB, TB>>>(src, dst, feat);    // 2

    k_fused<<<NT, 1024, FSMEM>>>(0, 0, b + 0 * DD, nullptr, 1);    // 3 <-- profiled
    k_fused<<<NT, 1024, FSMEM>>>(1, 1, b + 1 * DD, nullptr, 2);
    k_fused<<<NT, 1024, FSMEM>>>(2, 2, b + 2 * DD, nullptr, 1);
    k_fused<<<NT, 1024, FSMEM>>>(1, 3, b + 3 * DD, out, 0);
}